// round 14
// baseline (speedup 1.0000x reference)
#include <cuda_runtime.h>
#include <cuda_bf16.h>
#include <math.h>

#define TT   1024
#define NBAT 64
#define KD   512
#define G3   1536
#define SHP  520          // smem h pitch (elements)
#define NCTA 64           // recurrence CTAs
#define COLS 32           // G-columns per CTA (8 hidden units x 4 gate-planes)

// ---- static device scratch ----
__device__ float          g_GX[(size_t)TT * NBAT * G3];
__device__ __nv_bfloat16  g_H_hi[(size_t)(TT + 1) * NBAT * KD];
__device__ __nv_bfloat16  g_H_lo[(size_t)(TT + 1) * NBAT * KD];
__device__ __nv_bfloat16  g_X_hi[(size_t)NBAT * TT * KD];
__device__ __nv_bfloat16  g_X_lo[(size_t)NBAT * TT * KD];
__device__ float          g_Whp[G3 * KD];
__device__ float          g_bpf[G3];
__device__ __nv_bfloat16  g_Mp_hi[NCTA * COLS * KD];
__device__ __nv_bfloat16  g_Mp_lo[NCTA * COLS * KD];
__device__ float          g_biasA[NCTA * COLS];
__device__ float          g_bias0[NCTA * COLS];
__device__ __nv_bfloat16  g_Wx_hi[G3 * KD];
__device__ __nv_bfloat16  g_Wx_lo[G3 * KD];
__device__ __nv_bfloat16  g_Wp_hi[256 * KD];
__device__ __nv_bfloat16  g_Wp_lo[256 * KD];
__device__ unsigned       g_cnt[TT];    // per-step barrier counters (self-cleaning)
__device__ unsigned       g_fin;        // final cleanup round

__device__ __forceinline__ void split2(float v, __nv_bfloat16 &hi, __nv_bfloat16 &lo) {
    hi = __float2bfloat16(v);
    lo = __float2bfloat16(v - __bfloat162float(hi));
}

__device__ __forceinline__ void mma_bf16(float *d, const unsigned *a, const unsigned *b) {
    asm volatile(
        "mma.sync.aligned.m16n8k16.row.col.f32.bf16.bf16.f32 "
        "{%0,%1,%2,%3}, {%4,%5,%6,%7}, {%8,%9}, {%0,%1,%2,%3};\n"
        : "+f"(d[0]), "+f"(d[1]), "+f"(d[2]), "+f"(d[3])
        : "r"(a[0]), "r"(a[1]), "r"(a[2]), "r"(a[3]), "r"(b[0]), "r"(b[1]));
}

__device__ __forceinline__ unsigned smem_u32(const void *p) {
    return (unsigned)__cvta_generic_to_shared(p);
}

__device__ __forceinline__ void cp16(unsigned s, const void *g) {
    asm volatile("cp.async.cg.shared.global [%0], [%1], 16;\n" :: "r"(s), "l"(g));
}
#define CP_COMMIT() asm volatile("cp.async.commit_group;\n" ::: "memory")
#define CP_WAIT(n)  asm volatile("cp.async.wait_group %0;\n" :: "n"(n) : "memory")

__device__ __forceinline__ void ldsm4(unsigned *r, unsigned addr) {
    asm volatile("ldmatrix.sync.aligned.m8n8.x4.shared.b16 {%0,%1,%2,%3}, [%4];\n"
        : "=r"(r[0]), "=r"(r[1]), "=r"(r[2]), "=r"(r[3]) : "r"(addr));
}

__device__ __forceinline__ unsigned atom_add_gpu(unsigned *p, unsigned v) {
    unsigned old;
    asm volatile("atom.relaxed.gpu.add.u32 %0, [%1], %2;\n"
                 : "=r"(old) : "l"(p), "r"(v) : "memory");
    return old;
}

__device__ __forceinline__ unsigned ld_acq_gpu(const unsigned *p) {
    unsigned v;
    asm volatile("ld.acquire.gpu.u32 %0, [%1];\n" : "=r"(v) : "l"(p) : "memory");
    return v;
}

// ---- prep 1: W_hp = W_pf @ W_p ; bpf = W_pf @ b_p ----
__global__ void k_prep1(const float *__restrict__ Wih, const float *__restrict__ Wp,
                        const float *__restrict__ bp) {
    int idx = blockIdx.x * blockDim.x + threadIdx.x;
    if (idx < G3 * KD) {
        int j = idx >> 9, k = idx & 511;
        const float *wrow = Wih + (size_t)j * 768 + 512;
        float acc = 0.f;
#pragma unroll 4
        for (int p = 0; p < 256; p++) acc += wrow[p] * Wp[p * KD + k];
        g_Whp[idx] = acc;
        return;
    }
    int j = idx - G3 * KD;
    if (j < G3) {
        const float *wrow = Wih + (size_t)j * 768 + 512;
        float acc = 0.f;
        for (int p = 0; p < 256; p++) acc += wrow[p] * bp[p];
        g_bpf[j] = acc;
    }
}

// ---- prep 2: pack Mp/biases, split Wx, split Wp, split X, init h0/barriers ----
#define P0 (NCTA * COLS * KD)
#define P1 (G3 * KD)
#define P2 (256 * KD)
#define P3 ((size_t)NBAT * TT * KD)
#define P4 (NBAT * KD)
__global__ void k_prep2(const float *__restrict__ Wih, const float *__restrict__ Whh,
                        const float *__restrict__ bih, const float *__restrict__ bhh,
                        const float *__restrict__ Wp, const float *__restrict__ X) {
    size_t idx = (size_t)blockIdx.x * blockDim.x + threadIdx.x;

    if (idx < P0) {                                   // Mp + biases
        int k = (int)idx & 511;
        int c = ((int)idx >> 9) & 31;                 // column within CTA (COLS=32)
        int b = (int)(idx >> 14);                     // CTA id (9+5 bits below)
        int gsel = c >> 3, jj = c & 7;
        int j = b * 8 + jj;
        float v;
        if (gsel == 0)      v = Whh[j * KD + k] + g_Whp[j * KD + k];
        else if (gsel == 1) v = Whh[(512 + j) * KD + k] + g_Whp[(512 + j) * KD + k];
        else if (gsel == 2) v = g_Whp[(1024 + j) * KD + k];
        else                v = Whh[(1024 + j) * KD + k];
        __nv_bfloat16 hi, lo;
        split2(v, hi, lo);
        g_Mp_hi[idx] = hi;
        g_Mp_lo[idx] = lo;
        if (k == 0) {
            float bb, b0;
            if (gsel == 0)      { b0 = bih[j] + bhh[j];             bb = b0 + g_bpf[j]; }
            else if (gsel == 1) { b0 = bih[512 + j] + bhh[512 + j]; bb = b0 + g_bpf[512 + j]; }
            else if (gsel == 2) { b0 = bih[1024 + j];               bb = b0 + g_bpf[1024 + j]; }
            else                { b0 = bhh[1024 + j];               bb = b0; }
            g_biasA[b * COLS + c] = bb;
            g_bias0[b * COLS + c] = b0;
        }
        return;
    }
    idx -= P0;

    if (idx < P1) {                                   // Wx split
        int j = (int)(idx >> 9), k = (int)idx & 511;
        __nv_bfloat16 hi, lo;
        split2(Wih[(size_t)j * 768 + k], hi, lo);
        g_Wx_hi[idx] = hi;
        g_Wx_lo[idx] = lo;
        return;
    }
    idx -= P1;

    if (idx < P2) {                                   // Wp split
        __nv_bfloat16 hi, lo;
        split2(Wp[idx], hi, lo);
        g_Wp_hi[idx] = hi;
        g_Wp_lo[idx] = lo;
        return;
    }
    idx -= P2;

    if (idx < P3) {                                   // X split
        __nv_bfloat16 hi, lo;
        split2(X[idx], hi, lo);
        g_X_hi[idx] = hi;
        g_X_lo[idx] = lo;
        return;
    }
    idx -= P3;

    if (idx < P4) {                                   // h slot 0 = 0
        g_H_hi[idx] = __float2bfloat16(0.f);
        g_H_lo[idx] = __float2bfloat16(0.f);
        return;
    }
    idx -= P4;
    if (idx < TT) { g_cnt[idx] = 0u; return; }        // barrier counters
    if (idx == TT) g_fin = 0u;
}

// ---- GX = X @ Wx^T : grid (24,1024) x 256 threads, 64x64 tiles ----
__global__ void __launch_bounds__(256) k_gx() {
    int w = threadIdx.x >> 5, lane = threadIdx.x & 31;
    int g = lane >> 2, tg = lane & 3;
    int m0 = blockIdx.y * 64 + (w >> 1) * 16;
    int n0 = blockIdx.x * 64 + (w & 1) * 32;

    float acc[4][4];
#pragma unroll
    for (int i = 0; i < 4; i++)
#pragma unroll
        for (int q = 0; q < 4; q++) acc[i][q] = 0.f;

    const __nv_bfloat16 *a0h = g_X_hi + (size_t)(m0 + g) * KD;
    const __nv_bfloat16 *a1h = g_X_hi + (size_t)(m0 + g + 8) * KD;
    const __nv_bfloat16 *a0l = g_X_lo + (size_t)(m0 + g) * KD;
    const __nv_bfloat16 *a1l = g_X_lo + (size_t)(m0 + g + 8) * KD;

#pragma unroll 2
    for (int kc = 0; kc < KD; kc += 16) {
        unsigned ah[4], al[4];
        ah[0] = *(const unsigned *)(a0h + kc + tg * 2);
        ah[1] = *(const unsigned *)(a1h + kc + tg * 2);
        ah[2] = *(const unsigned *)(a0h + kc + tg * 2 + 8);
        ah[3] = *(const unsigned *)(a1h + kc + tg * 2 + 8);
        al[0] = *(const unsigned *)(a0l + kc + tg * 2);
        al[1] = *(const unsigned *)(a1l + kc + tg * 2);
        al[2] = *(const unsigned *)(a0l + kc + tg * 2 + 8);
        al[3] = *(const unsigned *)(a1l + kc + tg * 2 + 8);
#pragma unroll
        for (int nt = 0; nt < 4; nt++) {
            int col = n0 + nt * 8 + g;
            const __nv_bfloat16 *bh = g_Wx_hi + (size_t)col * KD + kc + tg * 2;
            const __nv_bfloat16 *bl = g_Wx_lo + (size_t)col * KD + kc + tg * 2;
            unsigned bhi[2] = { *(const unsigned *)bh, *(const unsigned *)(bh + 8) };
            unsigned blo[2] = { *(const unsigned *)bl, *(const unsigned *)(bl + 8) };
            mma_bf16(acc[nt], ah, bhi);
            mma_bf16(acc[nt], ah, blo);
            mma_bf16(acc[nt], al, bhi);
        }
    }

    int ma = m0 + g, mb = m0 + g + 8;
    size_t ra = (size_t)((ma & 1023) * 64 + (ma >> 10)) * G3;
    size_t rb = (size_t)((mb & 1023) * 64 + (mb >> 10)) * G3;
#pragma unroll
    for (int nt = 0; nt < 4; nt++) {
        int col = n0 + nt * 8 + tg * 2;
        *(float2 *)(g_GX + ra + col) = make_float2(acc[nt][0], acc[nt][1]);
        *(float2 *)(g_GX + rb + col) = make_float2(acc[nt][2], acc[nt][3]);
    }
}

// ---- recurrence v4: 64 CTAs x 256 threads, 32 G-columns (8 hidden units)/CTA ----
// smem layout (bytes):
//   sWb   [0, 65536)        packed b-frags: [plane][nt][kc32][sub][lane] uint2
//   sHhi  [65536, 132096)   64 x 520 bf16
//   sHlo  [132096, 198656)  64 x 520 bf16
//   sG    [198656, 207104)  64 x 33 float
//   sBias [207104, 207232) ; sBias0 [207232, 207360)
#define REC_SMEM 207360

__global__ void __launch_bounds__(256) k_rec() {
    extern __shared__ char smem[];
    uint2         *sWb  = (uint2 *)(smem);
    __nv_bfloat16 *sHhi = (__nv_bfloat16 *)(smem + 65536);
    __nv_bfloat16 *sHlo = (__nv_bfloat16 *)(smem + 132096);
    float         *sG   = (float *)(smem + 198656);
    float         *sBias  = (float *)(smem + 207104);
    float         *sBias0 = (float *)(smem + 207232);

    int b = blockIdx.x;
    int tid = threadIdx.x;
    int w = tid >> 5, lane = tid & 31;
    int g = lane >> 2, tg = lane & 3;

    // one-time: pack b-frags [plane][nt][kci][sub][lane]
    for (int idx = tid; idx < 8192; idx += 256) {
        int pl   = idx & 31;
        int sub  = (idx >> 5) & 1;
        int kci  = (idx >> 6) & 31;
        int nt   = (idx >> 11) & 1;
        int plane= idx >> 12;
        int c  = nt * 16 + sub * 8 + (pl >> 2);
        int k0 = kci * 16 + (pl & 3) * 2;
        const __nv_bfloat16 *row =
            (plane ? g_Mp_lo : g_Mp_hi) + (size_t)b * (COLS * KD) + c * 512;
        unsigned v0 = *(const unsigned *)(row + k0);
        unsigned v1 = *(const unsigned *)(row + k0 + 8);
        sWb[idx] = make_uint2(v0, v1);
    }
    if (tid < COLS) {
        sBias[tid]  = g_biasA[b * COLS + tid];
        sBias0[tid] = g_bias0[b * COLS + tid];
    }
    __syncthreads();

    int m0 = (w >> 1) * 16;     // batch-row tile
    int nt = w & 1;             // 16-col group
    int tile = lane >> 3;
    int lrow = m0 + ((tile & 1) << 3) + (lane & 7);
    int lcb  = (tile >> 1) * 8;
    unsigned aHiB = smem_u32(sHhi) + (unsigned)(lrow * SHP + lcb) * 2;
    unsigned aLoB = smem_u32(sHlo) + (unsigned)(lrow * SHP + lcb) * 2;
    const uint2 *wbH = sWb + (0 * 2 + nt) * 2048 + lane;
    const uint2 *wbL = sWb + (1 * 2 + nt) * 2048 + lane;

    unsigned sHhiU = smem_u32(sHhi);
    unsigned sHloU = smem_u32(sHlo);

    for (int t = 0; t < TT; t++) {
        // prefetch GX gate operands (2 items/thread x 3 gates)
        const float *GXt = g_GX + (size_t)t * (NBAT * G3);
        float gx_r[2], gx_z[2], gx_n[2];
#pragma unroll
        for (int it = 0; it < 2; it++) {
            int i = tid + it * 256;
            int n = i >> 3, jj = i & 7;
            int j = b * 8 + jj;
            gx_r[it] = GXt[n * G3 + j];
            gx_z[it] = GXt[n * G3 + 512 + j];
            gx_n[it] = GXt[n * G3 + 1024 + j];
        }

        const char *Hh = (const char *)g_H_hi + (size_t)t * 65536;
        const char *Hl = (const char *)g_H_lo + (size_t)t * 65536;

        // stage h: two K-halves of cp.async(16B)
#pragma unroll
        for (int half = 0; half < 2; half++) {
#pragma unroll
            for (int it = 0; it < 16; it++) {
                int q = tid + it * 256;
                int plane = q >> 11;
                int r = q & 2047;
                int row = r >> 5, ch = r & 31;
                const char *gsrc = (plane ? Hl : Hh) + row * 1024 + half * 512 + ch * 16;
                unsigned sdst = (plane ? sHloU : sHhiU)
                              + (unsigned)(row * (SHP * 2) + half * 512 + ch * 16);
                cp16(sdst, gsrc);
            }
            CP_COMMIT();
        }

        float accA[2][4], accB[2][4], accC[2][4];
#pragma unroll
        for (int s = 0; s < 2; s++)
#pragma unroll
            for (int q = 0; q < 4; q++) { accA[s][q] = 0.f; accB[s][q] = 0.f; accC[s][q] = 0.f; }

        unsigned ah[2][4], al[2][4];

        CP_WAIT(1);
        __syncthreads();
        ldsm4(ah[0], aHiB);
        ldsm4(al[0], aLoB);
#pragma unroll
        for (int kk = 0; kk < 16; kk++) {
            int p = kk & 1, pn = p ^ 1;
            if (kk < 15) {
                ldsm4(ah[pn], aHiB + (kk + 1) * 32);
                ldsm4(al[pn], aLoB + (kk + 1) * 32);
            }
            uint2 bh0 = wbH[kk * 64];
            uint2 bh1 = wbH[kk * 64 + 32];
            uint2 bl0 = wbL[kk * 64];
            uint2 bl1 = wbL[kk * 64 + 32];
            mma_bf16(accA[0], ah[p], (const unsigned *)&bh0);
            mma_bf16(accA[1], ah[p], (const unsigned *)&bh1);
            mma_bf16(accB[0], ah[p], (const unsigned *)&bl0);
            mma_bf16(accB[1], ah[p], (const unsigned *)&bl1);
            mma_bf16(accC[0], al[p], (const unsigned *)&bh0);
            mma_bf16(accC[1], al[p], (const unsigned *)&bh1);
        }

        CP_WAIT(0);
        __syncthreads();
        ldsm4(ah[0], aHiB + 16 * 32);
        ldsm4(al[0], aLoB + 16 * 32);
#pragma unroll
        for (int kk = 16; kk < 32; kk++) {
            int p = kk & 1, pn = p ^ 1;
            if (kk < 31) {
                ldsm4(ah[pn], aHiB + (kk + 1) * 32);
                ldsm4(al[pn], aLoB + (kk + 1) * 32);
            }
            uint2 bh0 = wbH[kk * 64];
            uint2 bh1 = wbH[kk * 64 + 32];
            uint2 bl0 = wbL[kk * 64];
            uint2 bl1 = wbL[kk * 64 + 32];
            mma_bf16(accA[0], ah[p], (const unsigned *)&bh0);
            mma_bf16(accA[1], ah[p], (const unsigned *)&bh1);
            mma_bf16(accB[0], ah[p], (const unsigned *)&bl0);
            mma_bf16(accB[1], ah[p], (const unsigned *)&bl1);
            mma_bf16(accC[0], al[p], (const unsigned *)&bh0);
            mma_bf16(accC[1], al[p], (const unsigned *)&bh1);
        }

        // epilogue: acc -> sG (pitch 33)
#pragma unroll
        for (int s = 0; s < 2; s++) {
            int c = nt * 16 + s * 8 + tg * 2;
            sG[(m0 + g) * 33 + c]         = accA[s][0] + accB[s][0] + accC[s][0];
            sG[(m0 + g) * 33 + c + 1]     = accA[s][1] + accB[s][1] + accC[s][1];
            sG[(m0 + g + 8) * 33 + c]     = accA[s][2] + accB[s][2] + accC[s][2];
            sG[(m0 + g + 8) * 33 + c + 1] = accA[s][3] + accB[s][3] + accC[s][3];
        }
        __syncthreads();

        // gates: 2 (n, jj) items per thread
        {
            const float *bias = (t == 0) ? sBias0 : sBias;
#pragma unroll
            for (int it = 0; it < 2; it++) {
                int i = tid + it * 256;
                int n = i >> 3, jj = i & 7;
                int j = b * 8 + jj;
                float pr = sG[n * 33 + jj]       + gx_r[it] + bias[jj];
                float pz = sG[n * 33 + 8 + jj]   + gx_z[it] + bias[8 + jj];
                float pi = sG[n * 33 + 16 + jj]  + gx_n[it] + bias[16 + jj];
                float ph = sG[n * 33 + 24 + jj]             + bias[24 + jj];
                float r = 1.f / (1.f + __expf(-pr));
                float z = 1.f / (1.f + __expf(-pz));
                float ex = __expf(2.f * (pi + r * ph));
                float gg = __fdividef(ex - 1.f, ex + 1.f);
                float hold = __bfloat162float(sHhi[n * SHP + j])
                           + __bfloat162float(sHlo[n * SHP + j]);
                float hn = (1.f - z) * gg + z * hold;
                __nv_bfloat16 hi, lo;
                split2(hn, hi, lo);
                size_t oidx = (size_t)(t + 1) * (NBAT * KD) + n * KD + j;
                g_H_hi[oidx] = hi;
                g_H_lo[oidx] = lo;
            }
        }

        // grid barrier: per-step counter, nanosleep backoff, self-cleaning
        __syncthreads();
        if (tid == 0) {
            asm volatile("fence.acq_rel.gpu;\n" ::: "memory");
            unsigned old = atom_add_gpu(&g_cnt[t], 1u);
            if (old == NCTA - 1) {
                if (t > 0) g_cnt[t - 1] = 0u;
            } else {
                int spins = 0;
                while (ld_acq_gpu(&g_cnt[t]) < (unsigned)NCTA) {
                    if (++spins > 4) __nanosleep(200);
                }
            }
        }
        __syncthreads();
    }

    // final cleanup round (replay-idempotent)
    if (tid == 0) {
        unsigned old = atom_add_gpu(&g_fin, 1u);
        if (old == NCTA - 1) {
            g_cnt[TT - 1] = 0u;
            g_fin = 0u;
        }
    }
}

// ---- out[n][t][p] = h_t @ Wp^T + b_p : grid (4,1024) x 256 threads ----
__global__ void __launch_bounds__(256) k_out(const float *__restrict__ bp,
                                             float *__restrict__ out) {
    int w = threadIdx.x >> 5, lane = threadIdx.x & 31;
    int g = lane >> 2, tg = lane & 3;
    int m0 = blockIdx.y * 64 + (w >> 1) * 16;   // m = t*64 + n
    int n0 = blockIdx.x * 64 + (w & 1) * 32;

    float acc[4][4];
#pragma unroll
    for (int i = 0; i < 4; i++)
#pragma unroll
        for (int q = 0; q < 4; q++) acc[i][q] = 0.f;

    const __nv_bfloat16 *a0h = g_H_hi + (size_t)(m0 + g + 64) * KD;
    const __nv_bfloat16 *a1h = g_H_hi + (size_t)(m0 + g + 8 + 64) * KD;
    const __nv_bfloat16 *a0l = g_H_lo + (size_t)(m0 + g + 64) * KD;
    const __nv_bfloat16 *a1l = g_H_lo + (size_t)(m0 + g + 8 + 64) * KD;

#pragma unroll 2
    for (int kc = 0; kc < KD; kc += 16) {
        unsigned ah[4], al[4];
        ah[0] = *(const unsigned *)(a0h + kc + tg * 2);
        ah[1] = *(const unsigned *)(a1h + kc + tg * 2);
        ah[2] = *(const unsigned *)(a0h + kc + tg * 2 + 8);
        ah[3] = *(const unsigned *)(a1h + kc + tg * 2 + 8);
        al[0] = *(const unsigned *)(a0l + kc + tg * 2);
        al[1] = *(const unsigned *)(a1l + kc + tg * 2);
        al[2] = *(const unsigned *)(a0l + kc + tg * 2 + 8);
        al[3] = *(const unsigned *)(a1l + kc + tg * 2 + 8);
#pragma unroll
        for (int nt = 0; nt < 4; nt++) {
            int col = n0 + nt * 8 + g;
            const __nv_bfloat16 *bh = g_Wp_hi + (size_t)col * KD + kc + tg * 2;
            const __nv_bfloat16 *bl = g_Wp_lo + (size_t)col * KD + kc + tg * 2;
            unsigned bhi[2] = { *(const unsigned *)bh, *(const unsigned *)(bh + 8) };
            unsigned blo[2] = { *(const unsigned *)bl, *(const unsigned *)(bl + 8) };
            mma_bf16(acc[nt], ah, bhi);
            mma_bf16(acc[nt], ah, blo);
            mma_bf16(acc[nt], al, bhi);
        }
    }

    int ma = m0 + g, mb = m0 + g + 8;
    size_t ra = (size_t)(ma & 63) * (TT * 256) + (size_t)(ma >> 6) * 256;
    size_t rb = (size_t)(mb & 63) * (TT * 256) + (size_t)(mb >> 6) * 256;
#pragma unroll
    for (int nt = 0; nt < 4; nt++) {
        int col = n0 + nt * 8 + tg * 2;
        float b0 = bp[col], b1 = bp[col + 1];
        *(float2 *)(out + ra + col) = make_float2(acc[nt][0] + b0, acc[nt][1] + b1);
        *(float2 *)(out + rb + col) = make_float2(acc[nt][2] + b0, acc[nt][3] + b1);
    }
}

extern "C" void kernel_launch(void* const* d_in, const int* in_sizes, int n_in,
                              void* d_out, int out_size) {
    const float *X   = (const float *)d_in[0];
    // d_in[1] = text_lengths (all == T; reference ignores them)
    const float *Wih = (const float *)d_in[2];
    const float *Whh = (const float *)d_in[3];
    const float *bih = (const float *)d_in[4];
    const float *bhh = (const float *)d_in[5];
    const float *Wp  = (const float *)d_in[6];
    const float *bp  = (const float *)d_in[7];
    float *out = (float *)d_out;

    static int smem_set = 0;
    if (!smem_set) {
        cudaFuncSetAttribute(k_rec, cudaFuncAttributeMaxDynamicSharedMemorySize, REC_SMEM);
        smem_set = 1;
    }

    int n1 = G3 * KD + G3;
    k_prep1<<<(n1 + 255) / 256, 256>>>(Wih, Wp, bp);

    size_t n2 = (size_t)P0 + P1 + P2 + P3 + P4 + TT + 1;
    k_prep2<<<(unsigned)((n2 + 255) / 256), 256>>>(Wih, Whh, bih, bhh, Wp, X);

    dim3 ggx(24, 1024);
    k_gx<<<ggx, 256>>>();

    k_rec<<<NCTA, 256, REC_SMEM>>>();

    dim3 gout(4, 1024);
    k_out<<<gout, 256>>>(bp, out);
}